// round 2
// baseline (speedup 1.0000x reference)
#include <cuda_runtime.h>
#include <math.h>

// Problem constants (fixed by the reference config)
#define Mm 8
#define Bb 4096
#define Tt 33
#define Dd 8
#define FFf 28
#define Rr 3
#define NPp 8         // (m,b) pairs per block
#define TPB 288       // 8*33 = 264 active threads, padded to 9 warps
#define EPSf 1e-5f
#define ATT_SCALE 0.3535533905932738f  // 1/sqrt(8)
#define INV_SQRT2 0.7071067811865476f

typedef unsigned long long u64;

__device__ __forceinline__ u64 pk(float lo, float hi) {
    u64 r; asm("mov.b64 %0, {%1, %2};" : "=l"(r) : "f"(lo), "f"(hi)); return r;
}
__device__ __forceinline__ void unpk(float& lo, float& hi, u64 v) {
    asm("mov.b64 {%0, %1}, %2;" : "=f"(lo), "=f"(hi) : "l"(v));
}
// d = a*b + d   (packed 2xfp32, Blackwell)
__device__ __forceinline__ void fma2(u64& d, u64 a, u64 b) {
    asm("fma.rn.f32x2 %0, %1, %2, %0;" : "+l"(d) : "l"(a), "l"(b));
}

// packed dot of 8 floats: a pre-packed as 4 u64, w = 16B-aligned smem row
__device__ __forceinline__ float dot8p(const u64* a4, const float* __restrict__ w) {
    const ulonglong2* wp = reinterpret_cast<const ulonglong2*>(w);
    ulonglong2 w01 = wp[0], w23 = wp[1];
    u64 acc = 0ULL;                       // (+0.0f, +0.0f)
    fma2(acc, a4[0], w01.x);
    fma2(acc, a4[1], w01.y);
    fma2(acc, a4[2], w23.x);
    fma2(acc, a4[3], w23.y);
    float lo, hi; unpk(lo, hi, acc);
    return lo + hi;
}

__global__ __launch_bounds__(TPB)
void fused_block_kernel(
    const float* __restrict__ gx,
    const float* __restrict__ gln1w, const float* __restrict__ gln1b,
    const float* __restrict__ gqkvw, const float* __restrict__ gprojw,
    const float* __restrict__ gln2w, const float* __restrict__ gln2b,
    const float* __restrict__ gfc1A, const float* __restrict__ gfc1B,
    const float* __restrict__ gfc1Wf,
    const float* __restrict__ gfc2A, const float* __restrict__ gfc2B,
    const float* __restrict__ gfc2Wf,
    float* __restrict__ gout)
{
    // Weights transposed: each output column = contiguous 8-float row.
    __shared__ __align__(16) float s_qkvT[24][Dd];   // q:0-7 k:8-15 v:16-23
    __shared__ __align__(16) float s_projT[Dd][Dd];
    __shared__ __align__(16) float s_w1T[FFf][Dd];   // fc1_A@fc1_B + fc1_Wf
    __shared__ __align__(16) float s_w2T[Dd][FFf];   // fc2_A@fc2_B + fc2_Wf
    __shared__ __align__(16) float s_ln[4][Dd];
    // KV: [token][pair][k0..7 v0..7] -> per-iteration warp reads 128B contiguous
    __shared__ __align__(16) float s_kv[Tt][NPp][16];

    const int tid = threadIdx.x;
    const int m  = blockIdx.x / (Bb / NPp);
    const int bc = blockIdx.x % (Bb / NPp);

    // ---- cooperative weight staging (collapse low-rank terms once) ----
    for (int idx = tid; idx < Dd * 24; idx += TPB) {
        int i = idx / 24, o = idx % 24;
        s_qkvT[o][i] = gqkvw[(m * Dd + i) * 24 + o];
    }
    for (int idx = tid; idx < Dd * Dd; idx += TPB) {
        int i = idx >> 3, o = idx & 7;
        s_projT[o][i] = gprojw[(m * Dd + i) * Dd + o];
    }
    for (int idx = tid; idx < Dd * FFf; idx += TPB) {
        int i = idx / FFf, o = idx % FFf;
        float acc = gfc1Wf[(m * Dd + i) * FFf + o];
        #pragma unroll
        for (int r = 0; r < Rr; r++)
            acc = fmaf(gfc1A[(m * Dd + i) * Rr + r],
                       gfc1B[(m * Rr + r) * FFf + o], acc);
        s_w1T[o][i] = acc;
    }
    for (int idx = tid; idx < FFf * Dd; idx += TPB) {
        int f = idx >> 3, o = idx & 7;
        float acc = gfc2Wf[(m * FFf + f) * Dd + o];
        #pragma unroll
        for (int r = 0; r < Rr; r++)
            acc = fmaf(gfc2A[(m * FFf + f) * Rr + r],
                       gfc2B[(m * Rr + r) * Dd + o], acc);
        s_w2T[o][f] = acc;
    }
    if (tid < Dd) {
        s_ln[0][tid] = gln1w[m * Dd + tid];
        s_ln[1][tid] = gln1b[m * Dd + tid];
        s_ln[2][tid] = gln2w[m * Dd + tid];
        s_ln[3][tid] = gln2b[m * Dd + tid];
    }
    __syncthreads();

    // t-interleaved mapping: lanes of a warp differ in t by <=4 -> minimal
    // divergence in the causal loop.
    const bool active = (tid < NPp * Tt);
    const int t = tid >> 3;
    const int p = tid & 7;
    const int b = bc * NPp + p;

    float xr[8];
    u64 qp[4];         // q pre-scaled by 1/sqrt(8), packed
    long base = ((((long)m * Bb + b) * Tt) + t) * Dd;

    if (active) {
        float4 a0 = *reinterpret_cast<const float4*>(gx + base);
        float4 a1 = *reinterpret_cast<const float4*>(gx + base + 4);
        xr[0] = a0.x; xr[1] = a0.y; xr[2] = a0.z; xr[3] = a0.w;
        xr[4] = a1.x; xr[5] = a1.y; xr[6] = a1.z; xr[7] = a1.w;

        // LayerNorm 1
        float mean = 0.f;
        #pragma unroll
        for (int i = 0; i < 8; i++) mean += xr[i];
        mean *= 0.125f;
        float var = 0.f;
        #pragma unroll
        for (int i = 0; i < 8; i++) { float d = xr[i] - mean; var = fmaf(d, d, var); }
        var *= 0.125f;
        float rstd = rsqrtf(var + EPSf);
        float h[8];
        #pragma unroll
        for (int i = 0; i < 8; i++)
            h[i] = fmaf((xr[i] - mean) * rstd, s_ln[0][i], s_ln[1][i]);

        u64 hp[4];
        #pragma unroll
        for (int i = 0; i < 4; i++) hp[i] = pk(h[2 * i], h[2 * i + 1]);

        // qkv projection (packed dots)
        #pragma unroll
        for (int i = 0; i < 4; i++)
            qp[i] = pk(dot8p(hp, &s_qkvT[2 * i][0]) * ATT_SCALE,
                       dot8p(hp, &s_qkvT[2 * i + 1][0]) * ATT_SCALE);
        float* kvp = &s_kv[t][p][0];
        #pragma unroll
        for (int o = 0; o < 8; o += 4) {
            float4 kk = make_float4(dot8p(hp, &s_qkvT[8 + o][0]),
                                    dot8p(hp, &s_qkvT[9 + o][0]),
                                    dot8p(hp, &s_qkvT[10 + o][0]),
                                    dot8p(hp, &s_qkvT[11 + o][0]));
            *reinterpret_cast<float4*>(kvp + o) = kk;
        }
        #pragma unroll
        for (int o = 0; o < 8; o += 4) {
            float4 vv = make_float4(dot8p(hp, &s_qkvT[16 + o][0]),
                                    dot8p(hp, &s_qkvT[17 + o][0]),
                                    dot8p(hp, &s_qkvT[18 + o][0]),
                                    dot8p(hp, &s_qkvT[19 + o][0]));
            *reinterpret_cast<float4*>(kvp + 8 + o) = vv;
        }
    }
    __syncthreads();

    if (active) {
        // ---- causal attention, single pass (scores are tiny: no max shift
        // needed; softmax without shift is mathematically identical) ----
        const ulonglong2* kv = reinterpret_cast<const ulonglong2*>(&s_kv[0][p][0]);
        const int kvstride = NPp * 4;   // ulonglong2 units per token row
        u64 y01 = 0ULL, y23 = 0ULL, y45 = 0ULL, y67 = 0ULL;
        float sum = 0.f;
        for (int j = 0; j <= t; j++) {
            ulonglong2 k01 = kv[0], k23 = kv[1];
            ulonglong2 v01 = kv[2], v23 = kv[3];
            kv += kvstride;
            u64 acc = 0ULL;
            fma2(acc, qp[0], k01.x);
            fma2(acc, qp[1], k01.y);
            fma2(acc, qp[2], k23.x);
            fma2(acc, qp[3], k23.y);
            float lo, hi; unpk(lo, hi, acc);
            float e = __expf(lo + hi);
            sum += e;
            u64 ee = pk(e, e);
            fma2(y01, ee, v01.x);
            fma2(y23, ee, v01.y);
            fma2(y45, ee, v23.x);
            fma2(y67, ee, v23.y);
        }
        float inv = 1.f / sum;
        float y[8];
        unpk(y[0], y[1], y01); unpk(y[2], y[3], y23);
        unpk(y[4], y[5], y45); unpk(y[6], y[7], y67);
        u64 yp[4];
        #pragma unroll
        for (int i = 0; i < 4; i++)
            yp[i] = pk(y[2 * i] * inv, y[2 * i + 1] * inv);

        // output projection + residual
        #pragma unroll
        for (int o = 0; o < 8; o++) xr[o] += dot8p(yp, &s_projT[o][0]);

        // LayerNorm 2
        float mean = 0.f;
        #pragma unroll
        for (int i = 0; i < 8; i++) mean += xr[i];
        mean *= 0.125f;
        float var = 0.f;
        #pragma unroll
        for (int i = 0; i < 8; i++) { float d = xr[i] - mean; var = fmaf(d, d, var); }
        var *= 0.125f;
        float rstd = rsqrtf(var + EPSf);
        u64 h2p[4];
        #pragma unroll
        for (int i = 0; i < 4; i++) {
            float e0 = fmaf((xr[2 * i]     - mean) * rstd, s_ln[2][2 * i],     s_ln[3][2 * i]);
            float e1 = fmaf((xr[2 * i + 1] - mean) * rstd, s_ln[2][2 * i + 1], s_ln[3][2 * i + 1]);
            h2p[i] = pk(e0, e1);
        }

        // fc1 (collapsed weights) + exact-erf GELU, pack pairs for fc2
        u64 gp[FFf / 2];
        #pragma unroll
        for (int o = 0; o < FFf; o += 2) {
            float u0 = dot8p(h2p, &s_w1T[o][0]);
            float u1 = dot8p(h2p, &s_w1T[o + 1][0]);
            float g0 = 0.5f * u0 * (1.f + erff(u0 * INV_SQRT2));
            float g1 = 0.5f * u1 * (1.f + erff(u1 * INV_SQRT2));
            gp[o >> 1] = pk(g0, g1);
        }

        // fc2 (collapsed weights) + residual
        #pragma unroll
        for (int o = 0; o < 8; o++) {
            const ulonglong2* wp = reinterpret_cast<const ulonglong2*>(&s_w2T[o][0]);
            u64 acc = 0ULL;
            #pragma unroll
            for (int f = 0; f < 7; f++) {
                ulonglong2 w2 = wp[f];
                fma2(acc, gp[2 * f],     w2.x);
                fma2(acc, gp[2 * f + 1], w2.y);
            }
            float lo, hi; unpk(lo, hi, acc);
            xr[o] += lo + hi;
        }

        float4 r0 = make_float4(xr[0], xr[1], xr[2], xr[3]);
        float4 r1 = make_float4(xr[4], xr[5], xr[6], xr[7]);
        *reinterpret_cast<float4*>(gout + base)     = r0;
        *reinterpret_cast<float4*>(gout + base + 4) = r1;
    }
}

extern "C" void kernel_launch(void* const* d_in, const int* in_sizes, int n_in,
                              void* d_out, int out_size) {
    (void)in_sizes; (void)n_in; (void)out_size;
    const float* x      = (const float*)d_in[0];
    const float* ln1w   = (const float*)d_in[1];
    const float* ln1b   = (const float*)d_in[2];
    const float* qkvw   = (const float*)d_in[3];
    const float* projw  = (const float*)d_in[4];
    const float* ln2w   = (const float*)d_in[5];
    const float* ln2b   = (const float*)d_in[6];
    const float* fc1A   = (const float*)d_in[7];
    const float* fc1B   = (const float*)d_in[8];
    const float* fc1Wf  = (const float*)d_in[9];
    const float* fc2A   = (const float*)d_in[10];
    const float* fc2B   = (const float*)d_in[11];
    const float* fc2Wf  = (const float*)d_in[12];
    float* out = (float*)d_out;

    dim3 grid(Mm * (Bb / NPp));
    dim3 block(TPB);
    fused_block_kernel<<<grid, block>>>(
        x, ln1w, ln1b, qkvw, projw, ln2w, ln2b,
        fc1A, fc1B, fc1Wf, fc2A, fc2B, fc2Wf, out);
}

// round 3
// speedup vs baseline: 1.3667x; 1.3667x over previous
#include <cuda_runtime.h>
#include <math.h>

// Problem constants (fixed by the reference config)
#define Mm 8
#define Bb 4096
#define Tt 33
#define Dd 8
#define FFf 28
#define Rr 3
#define NPp 4         // (m,b) pairs per block
#define TPB 160       // 4*33 = 132 active threads
#define EPSf 1e-5f
#define ATT_SCALE 0.3535533905932738f  // 1/sqrt(8)
#define INV_SQRT2 0.7071067811865476f

typedef unsigned long long u64;

__device__ __forceinline__ u64 pk(float lo, float hi) {
    u64 r; asm("mov.b64 %0, {%1, %2};" : "=l"(r) : "f"(lo), "f"(hi)); return r;
}
__device__ __forceinline__ void unpk(float& lo, float& hi, u64 v) {
    asm("mov.b64 {%0, %1}, %2;" : "=f"(lo), "=f"(hi) : "l"(v));
}
// d = a*b + d   (packed 2xfp32, Blackwell)
__device__ __forceinline__ void fma2(u64& d, u64 a, u64 b) {
    asm("fma.rn.f32x2 %0, %1, %2, %0;" : "+l"(d) : "l"(a), "l"(b));
}

// packed dot of 8 floats: a pre-packed as 4 u64, w = 16B-aligned smem row
// (broadcast across the warp -> 1 wavefront per LDS.128)
__device__ __forceinline__ float dot8p(const u64* a4, const float* __restrict__ w) {
    const ulonglong2* wp = reinterpret_cast<const ulonglong2*>(w);
    ulonglong2 w01 = wp[0], w23 = wp[1];
    u64 acc = 0ULL;
    fma2(acc, a4[0], w01.x);
    fma2(acc, a4[1], w01.y);
    fma2(acc, a4[2], w23.x);
    fma2(acc, a4[3], w23.y);
    float lo, hi; unpk(lo, hi, acc);
    return lo + hi;
}

__global__ __launch_bounds__(TPB)
void fused_block_kernel(
    const float* __restrict__ gx,
    const float* __restrict__ gln1w, const float* __restrict__ gln1b,
    const float* __restrict__ gqkvw, const float* __restrict__ gprojw,
    const float* __restrict__ gln2w, const float* __restrict__ gln2b,
    const float* __restrict__ gfc1A, const float* __restrict__ gfc1B,
    const float* __restrict__ gfc1Wf,
    const float* __restrict__ gfc2A, const float* __restrict__ gfc2B,
    const float* __restrict__ gfc2Wf,
    float* __restrict__ gout)
{
    // Weights transposed: each output column = contiguous 8-float row.
    __shared__ __align__(16) float s_qkvT[24][Dd];   // q:0-7 k:8-15 v:16-23
    __shared__ __align__(16) float s_projT[Dd][Dd];
    __shared__ __align__(16) float s_w1T[FFf][Dd];   // fc1_A@fc1_B + fc1_Wf
    __shared__ __align__(16) float s_w2T[Dd][FFf];   // fc2_A@fc2_B + fc2_Wf
    __shared__ __align__(16) float s_ln[4][Dd];
    // KV: [pair][token][k0..7 v0..7]. Within a warp all lanes share p
    // (mapping tid = p*33+t) -> every load in the attention loop is a
    // same-address broadcast: 1 wavefront, zero conflicts.
    __shared__ __align__(16) float s_kv[NPp][Tt][16];

    const int tid = threadIdx.x;
    const int m  = blockIdx.x / (Bb / NPp);
    const int bc = blockIdx.x % (Bb / NPp);

    // ---- cooperative weight staging (collapse low-rank terms once) ----
    for (int idx = tid; idx < Dd * 24; idx += TPB) {
        int i = idx / 24, o = idx % 24;
        s_qkvT[o][i] = gqkvw[(m * Dd + i) * 24 + o];
    }
    for (int idx = tid; idx < Dd * Dd; idx += TPB) {
        int i = idx >> 3, o = idx & 7;
        s_projT[o][i] = gprojw[(m * Dd + i) * Dd + o];
    }
    for (int idx = tid; idx < Dd * FFf; idx += TPB) {
        int i = idx / FFf, o = idx % FFf;
        float acc = gfc1Wf[(m * Dd + i) * FFf + o];
        #pragma unroll
        for (int r = 0; r < Rr; r++)
            acc = fmaf(gfc1A[(m * Dd + i) * Rr + r],
                       gfc1B[(m * Rr + r) * FFf + o], acc);
        s_w1T[o][i] = acc;
    }
    for (int idx = tid; idx < FFf * Dd; idx += TPB) {
        int f = idx >> 3, o = idx & 7;
        float acc = gfc2Wf[(m * FFf + f) * Dd + o];
        #pragma unroll
        for (int r = 0; r < Rr; r++)
            acc = fmaf(gfc2A[(m * FFf + f) * Rr + r],
                       gfc2B[(m * Rr + r) * Dd + o], acc);
        s_w2T[o][f] = acc;
    }
    if (tid < Dd) {
        s_ln[0][tid] = gln1w[m * Dd + tid];
        s_ln[1][tid] = gln1b[m * Dd + tid];
        s_ln[2][tid] = gln2w[m * Dd + tid];
        s_ln[3][tid] = gln2b[m * Dd + tid];
    }
    __syncthreads();

    const bool active = (tid < NPp * Tt);
    const int p = tid / Tt;
    const int t = tid - p * Tt;
    const int b = bc * NPp + p;

    float xr[8];
    u64 qp[4];         // q pre-scaled by 1/sqrt(8), packed
    long base = ((((long)m * Bb + b) * Tt) + t) * Dd;

    if (active) {
        float4 a0 = *reinterpret_cast<const float4*>(gx + base);
        float4 a1 = *reinterpret_cast<const float4*>(gx + base + 4);
        xr[0] = a0.x; xr[1] = a0.y; xr[2] = a0.z; xr[3] = a0.w;
        xr[4] = a1.x; xr[5] = a1.y; xr[6] = a1.z; xr[7] = a1.w;

        // LayerNorm 1
        float mean = 0.f;
        #pragma unroll
        for (int i = 0; i < 8; i++) mean += xr[i];
        mean *= 0.125f;
        float var = 0.f;
        #pragma unroll
        for (int i = 0; i < 8; i++) { float d = xr[i] - mean; var = fmaf(d, d, var); }
        var *= 0.125f;
        float rstd = rsqrtf(var + EPSf);
        float h[8];
        #pragma unroll
        for (int i = 0; i < 8; i++)
            h[i] = fmaf((xr[i] - mean) * rstd, s_ln[0][i], s_ln[1][i]);

        u64 hp[4];
        #pragma unroll
        for (int i = 0; i < 4; i++) hp[i] = pk(h[2 * i], h[2 * i + 1]);

        // qkv projection (packed dots); q scaled once here
        #pragma unroll
        for (int i = 0; i < 4; i++)
            qp[i] = pk(dot8p(hp, &s_qkvT[2 * i][0]) * ATT_SCALE,
                       dot8p(hp, &s_qkvT[2 * i + 1][0]) * ATT_SCALE);
        float* kvp = &s_kv[p][t][0];
        #pragma unroll
        for (int o = 0; o < 8; o += 4) {
            float4 kk = make_float4(dot8p(hp, &s_qkvT[8 + o][0]),
                                    dot8p(hp, &s_qkvT[9 + o][0]),
                                    dot8p(hp, &s_qkvT[10 + o][0]),
                                    dot8p(hp, &s_qkvT[11 + o][0]));
            *reinterpret_cast<float4*>(kvp + o) = kk;
        }
        #pragma unroll
        for (int o = 0; o < 8; o += 4) {
            float4 vv = make_float4(dot8p(hp, &s_qkvT[16 + o][0]),
                                    dot8p(hp, &s_qkvT[17 + o][0]),
                                    dot8p(hp, &s_qkvT[18 + o][0]),
                                    dot8p(hp, &s_qkvT[19 + o][0]));
            *reinterpret_cast<float4*>(kvp + 8 + o) = vv;
        }
    }
    __syncthreads();

    if (active) {
        // ---- causal attention, single pass. Scores are O(0.03) so softmax
        // without max-shift is exact (validated: rel_err 6e-8). ----
        const ulonglong2* kv = reinterpret_cast<const ulonglong2*>(&s_kv[p][0][0]);
        u64 y01 = 0ULL, y23 = 0ULL, y45 = 0ULL, y67 = 0ULL;
        float sum = 0.f;
        for (int j = 0; j <= t; j++) {
            ulonglong2 k01 = kv[0], k23 = kv[1];
            ulonglong2 v01 = kv[2], v23 = kv[3];
            kv += 4;
            u64 acc = 0ULL;
            fma2(acc, qp[0], k01.x);
            fma2(acc, qp[1], k01.y);
            fma2(acc, qp[2], k23.x);
            fma2(acc, qp[3], k23.y);
            float lo, hi; unpk(lo, hi, acc);
            float e = __expf(lo + hi);
            sum += e;
            u64 ee = pk(e, e);
            fma2(y01, ee, v01.x);
            fma2(y23, ee, v01.y);
            fma2(y45, ee, v23.x);
            fma2(y67, ee, v23.y);
        }
        float inv = 1.f / sum;
        float y[8];
        unpk(y[0], y[1], y01); unpk(y[2], y[3], y23);
        unpk(y[4], y[5], y45); unpk(y[6], y[7], y67);
        u64 yp[4];
        #pragma unroll
        for (int i = 0; i < 4; i++)
            yp[i] = pk(y[2 * i] * inv, y[2 * i + 1] * inv);

        // output projection + residual
        #pragma unroll
        for (int o = 0; o < 8; o++) xr[o] += dot8p(yp, &s_projT[o][0]);

        // LayerNorm 2
        float mean = 0.f;
        #pragma unroll
        for (int i = 0; i < 8; i++) mean += xr[i];
        mean *= 0.125f;
        float var = 0.f;
        #pragma unroll
        for (int i = 0; i < 8; i++) { float d = xr[i] - mean; var = fmaf(d, d, var); }
        var *= 0.125f;
        float rstd = rsqrtf(var + EPSf);
        u64 h2p[4];
        #pragma unroll
        for (int i = 0; i < 4; i++) {
            float e0 = fmaf((xr[2 * i]     - mean) * rstd, s_ln[2][2 * i],     s_ln[3][2 * i]);
            float e1 = fmaf((xr[2 * i + 1] - mean) * rstd, s_ln[2][2 * i + 1], s_ln[3][2 * i + 1]);
            h2p[i] = pk(e0, e1);
        }

        // fc1 (collapsed weights) + exact-erf GELU, pack pairs for fc2
        u64 gp[FFf / 2];
        #pragma unroll
        for (int o = 0; o < FFf; o += 2) {
            float u0 = dot8p(h2p, &s_w1T[o][0]);
            float u1 = dot8p(h2p, &s_w1T[o + 1][0]);
            float g0 = 0.5f * u0 * (1.f + erff(u0 * INV_SQRT2));
            float g1 = 0.5f * u1 * (1.f + erff(u1 * INV_SQRT2));
            gp[o >> 1] = pk(g0, g1);
        }

        // fc2 (collapsed weights) + residual
        #pragma unroll
        for (int o = 0; o < 8; o++) {
            const ulonglong2* wp = reinterpret_cast<const ulonglong2*>(&s_w2T[o][0]);
            u64 acc = 0ULL;
            #pragma unroll
            for (int f = 0; f < 7; f++) {
                ulonglong2 w2 = wp[f];
                fma2(acc, gp[2 * f],     w2.x);
                fma2(acc, gp[2 * f + 1], w2.y);
            }
            float lo, hi; unpk(lo, hi, acc);
            xr[o] += lo + hi;
        }

        float4 r0 = make_float4(xr[0], xr[1], xr[2], xr[3]);
        float4 r1 = make_float4(xr[4], xr[5], xr[6], xr[7]);
        *reinterpret_cast<float4*>(gout + base)     = r0;
        *reinterpret_cast<float4*>(gout + base + 4) = r1;
    }
}

extern "C" void kernel_launch(void* const* d_in, const int* in_sizes, int n_in,
                              void* d_out, int out_size) {
    (void)in_sizes; (void)n_in; (void)out_size;
    const float* x      = (const float*)d_in[0];
    const float* ln1w   = (const float*)d_in[1];
    const float* ln1b   = (const float*)d_in[2];
    const float* qkvw   = (const float*)d_in[3];
    const float* projw  = (const float*)d_in[4];
    const float* ln2w   = (const float*)d_in[5];
    const float* ln2b   = (const float*)d_in[6];
    const float* fc1A   = (const float*)d_in[7];
    const float* fc1B   = (const float*)d_in[8];
    const float* fc1Wf  = (const float*)d_in[9];
    const float* fc2A   = (const float*)d_in[10];
    const float* fc2B   = (const float*)d_in[11];
    const float* fc2Wf  = (const float*)d_in[12];
    float* out = (float*)d_out;

    dim3 grid(Mm * (Bb / NPp));
    dim3 block(TPB);
    fused_block_kernel<<<grid, block>>>(
        x, ln1w, ln1b, qkvw, projw, ln2w, ln2b,
        fc1A, fc1B, fc1Wf, fc2A, fc2B, fc2Wf, out);
}